// round 15
// baseline (speedup 1.0000x reference)
#include <cuda_runtime.h>
#include <cuda_bf16.h>
#include <cstdint>

#define Vv 32000
#define Hh 256
#define Ss 2048
#define Bb 128
#define BV (Bb*Vv)
#define NBLK 250           // gemm_logits blocks
#define NP   (NBLK*2)      // partial-softmax columns per row (2 n-halves/block)

// gemm_logits smem: 4 stages * (A 128x12 + B 8x136) words
#define ASTw 1536          // words per A stage (128*12) — bf16 pairs, stride 12
#define BSTw 1088          // words per B stage (8*136) — bf16 pairs, stride 136
#define NSTG 4
#define SMEMB (NSTG*(ASTw+BSTw)*4)

// ---------------- scratch (static __device__, no allocation) ----------------
__device__ float g_ctx[Bb*Hh];
__device__ float g_xcat[Bb*512];
__device__ float g_scores[Bb*Ss];
__device__ float g_partM[Bb*4];
__device__ float g_partL[Bb*4];
__device__ float g_ctxPart[Bb*4*Hh];
__device__ float g_gAp[4*Bb*768];   // split-K partials (no bias)
__device__ float g_gBp[4*Bb*768];
__device__ float g_pM[Bb*NP];       // per-block logit max partials
__device__ float g_pL[Bb*NP];       // per-block sumexp partials
__device__ __align__(16) uint32_t g_catB[Bb*256];        // [h_new, ctx] bf16x2
__device__ __align__(16) uint32_t g_Wbf[256*Vv];         // outW as bf16 k-pairs [kp][v]

__device__ __forceinline__ uint32_t tf32u(float x) {
    uint32_t u;
    asm("cvt.rna.tf32.f32 %0, %1;" : "=r"(u) : "f"(x));
    return u;
}

__device__ __forceinline__ uint32_t bf16pack(float lo, float hi) {
    uint32_t r;
    asm("cvt.rn.bf16x2.f32 %0, %1, %2;" : "=r"(r) : "f"(hi), "f"(lo));
    return r;
}

__device__ __forceinline__ void l2_prefetch(const void* p) {
    asm volatile("prefetch.global.L2 [%0];" :: "l"(p));
}

// ---------------- K1a: flash attention partials + outW bf16 conversion ------
// sc in [0,4): attention over a 512-s chunk (computes q in-block; enc via .cs)
// sc in [4,8): convert outW -> g_Wbf (bf16 k-pair packed), 512 slices total
// sc == 8   : prefetch W_ih, W_hh into L2
__global__ void __launch_bounds__(512) attn_partial(const float* __restrict__ enc,
        const float* __restrict__ hidden, const float* __restrict__ attnW,
        const float* __restrict__ outW, const float* __restrict__ W_ih,
        const float* __restrict__ W_hh) {
    int b = blockIdx.y, sc = blockIdx.x;
    int tid = threadIdx.x;

    if (sc >= 4) {
        if (sc < 8) {
            int pid = (sc - 4)*Bb + b;          // 0..511
            int kp = pid >> 1;                  // 0..255
            int vbase = (pid & 1) * (Vv/2);
            const float* r0 = outW + (long)(2*kp    )*Vv + vbase;
            const float* r1 = outW + (long)(2*kp + 1)*Vv + vbase;
            uint32_t* dst = g_Wbf + (long)kp*Vv + vbase;
            for (int t = tid; t < Vv/2; t += 512) {
                float f0 = __ldcs(r0 + t);
                float f1 = __ldcs(r1 + t);
                dst[t] = bf16pack(f0, f1);
            }
        } else {
            const float* s1 = W_ih + (long)b*3072;
            for (int t = tid; t < 96; t += 512)
                l2_prefetch(s1 + t*32);
            const float* s2 = W_hh + (long)b*1536;
            for (int t = tid; t < 48; t += 512)
                l2_prefetch(s2 + t*32);
        }
        return;
    }

    int w = tid >> 5, lane = tid & 31;
    __shared__ float qs[Hh];
    __shared__ float wm[16], wl[16];
    __shared__ float wctx[16][Hh];

    // ---- compute q[b,:] = hidden[b,:] @ We (We = attn_W[:, H:]) in-block ----
    {
        int h = tid >> 1, half = tid & 1;
        const float* hr = hidden + b*Hh;
        const float* Wcol = attnW + 256 + h;     // [k][256+h], row stride 512
        float part = 0.f;
        int k0 = half * 128;
#pragma unroll 4
        for (int k = 0; k < 128; k++)
            part += hr[k0 + k] * Wcol[(long)(k0 + k)*512];
        float* qred = &wctx[0][0];               // reuse wctx before its real use
        qred[tid] = part;
        __syncthreads();
        if (tid < 256) qs[tid] = qred[2*tid] + qred[2*tid + 1];
        __syncthreads();
    }

    float qv[8];
#pragma unroll
    for (int k = 0; k < 8; k++) qv[k] = qs[lane*8 + k];

    const float* encb = enc + (long)b*Hh + (long)sc*512*(Bb*Hh) + lane*8;
    float m = -1e30f, l = 0.f;
    float c[8];
#pragma unroll
    for (int k = 0; k < 8; k++) c[k] = 0.f;

    for (int j0 = 0; j0 < 32; j0 += 4) {
        float e[4][8];
#pragma unroll
        for (int jj = 0; jj < 4; jj++) {
            const float* p = encb + (long)(w + 16*(j0+jj))*(Bb*Hh);
            float4 x0 = __ldcs((const float4*)p);
            float4 x1 = __ldcs((const float4*)(p+4));
            e[jj][0]=x0.x; e[jj][1]=x0.y; e[jj][2]=x0.z; e[jj][3]=x0.w;
            e[jj][4]=x1.x; e[jj][5]=x1.y; e[jj][6]=x1.z; e[jj][7]=x1.w;
        }
#pragma unroll
        for (int jj = 0; jj < 4; jj++) {
            float part = 0.f;
#pragma unroll
            for (int k = 0; k < 8; k++) part += e[jj][k]*qv[k];
#pragma unroll
            for (int o = 16; o; o >>= 1) part += __shfl_xor_sync(0xffffffffu, part, o);
            if (lane == 0) g_scores[b*Ss + sc*512 + w + 16*(j0+jj)] = part;
            float nm  = fmaxf(m, part);
            float scl = __expf(m - nm);
            float p_  = __expf(part - nm);
            l = l*scl + p_;
#pragma unroll
            for (int k = 0; k < 8; k++) c[k] = c[k]*scl + p_*e[jj][k];
            m = nm;
        }
    }
    if (lane == 0) { wm[w] = m; wl[w] = l; }
#pragma unroll
    for (int k = 0; k < 8; k++) wctx[w][lane*8+k] = c[k];
    __syncthreads();
    if (tid < Hh) {
        float gm = -1e30f;
        for (int i = 0; i < 16; i++) gm = fmaxf(gm, wm[i]);
        float L = 0.f, cv = 0.f;
        for (int i = 0; i < 16; i++) {
            float f = __expf(wm[i] - gm);
            L  += wl[i]*f;
            cv += wctx[i][tid]*f;
        }
        g_ctxPart[(b*4+sc)*Hh + tid] = cv;
        if (tid == 0) { g_partM[b*4+sc] = gm; g_partL[b*4+sc] = L; }
    }
}

// ---------------- K1b: combine partials, write attn_weights + context + xcat
__global__ void __launch_bounds__(256) attn_combine(const int* __restrict__ ids,
                                                    const float* __restrict__ emb,
                                                    float* __restrict__ out) {
    int b = blockIdx.x, tid = threadIdx.x;
    float m0 = g_partM[b*4+0], m1 = g_partM[b*4+1], m2 = g_partM[b*4+2], m3 = g_partM[b*4+3];
    float gm = fmaxf(fmaxf(m0,m1), fmaxf(m2,m3));
    float f0 = __expf(m0-gm), f1 = __expf(m1-gm), f2 = __expf(m2-gm), f3 = __expf(m3-gm);
    float L = g_partL[b*4+0]*f0 + g_partL[b*4+1]*f1 + g_partL[b*4+2]*f2 + g_partL[b*4+3]*f3;
    float cv = g_ctxPart[(b*4+0)*Hh+tid]*f0 + g_ctxPart[(b*4+1)*Hh+tid]*f1
             + g_ctxPart[(b*4+2)*Hh+tid]*f2 + g_ctxPart[(b*4+3)*Hh+tid]*f3;
    float ctx = cv / L;
    g_ctx[b*Hh + tid] = ctx;
    g_xcat[b*512 + tid]       = emb[(long)ids[b]*Hh + tid];
    g_xcat[b*512 + 256 + tid] = ctx;
    float invL = 1.f / L;
    for (int s = tid; s < Ss; s += 256)
        out[BV + Bb*Hh + b*Ss + s] = __expf(g_scores[b*Ss+s] - gm) * invL;
}

// ---------------- K2: gates TF32 GEMM, split-K x4 ---------------------------
__global__ void __launch_bounds__(256) gates_mma(const float* __restrict__ hidden,
        const float* __restrict__ W_ih, const float* __restrict__ W_hh) {
    __shared__ uint32_t As[2][128*36];
    __shared__ uint32_t Bs[2][32*36];

    int phase = blockIdx.y, z = blockIdx.z;
    const float* SRC  = phase ? hidden : g_xcat;
    const float* WPTR = phase ? W_hh   : W_ih;
    float*       dst  = (phase ? g_gBp : g_gAp) + z*(Bb*768);
    int LD = phase ? 256 : 512;
    int KT = phase ? 2   : 4;
    int kbase = z * KT * 32;

    int n0  = blockIdx.x * 32;
    int tid = threadIdx.x;
    int w = tid >> 5, lane = tid & 31;
    int wm = (w >> 1) * 32, wn = (w & 1) * 16;
    int g = lane >> 2, i4 = lane & 3;

    int arow = tid >> 3, acol = (tid & 7) * 4;
    int brow = tid >> 3, bcol = (tid & 7) * 4;

    float accA[2][2][4];
#pragma unroll
    for (int mt = 0; mt < 2; mt++)
#pragma unroll
        for (int nt = 0; nt < 2; nt++)
#pragma unroll
            for (int c = 0; c < 4; c++) accA[mt][nt][c] = 0.f;

    float4 ra[4]; float4 rb;
#pragma unroll
    for (int it = 0; it < 4; it++)
        ra[it] = *(const float4*)(SRC + (long)(arow + it*32)*LD + kbase + acol);
    rb = *(const float4*)(WPTR + (long)(n0 + brow)*LD + kbase + bcol);
#pragma unroll
    for (int it = 0; it < 4; it++) {
        int r = arow + it*32;
        As[0][r*36+acol+0] = tf32u(ra[it].x); As[0][r*36+acol+1] = tf32u(ra[it].y);
        As[0][r*36+acol+2] = tf32u(ra[it].z); As[0][r*36+acol+3] = tf32u(ra[it].w);
    }
    Bs[0][brow*36+bcol+0] = tf32u(rb.x); Bs[0][brow*36+bcol+1] = tf32u(rb.y);
    Bs[0][brow*36+bcol+2] = tf32u(rb.z); Bs[0][brow*36+bcol+3] = tf32u(rb.w);
    __syncthreads();

    for (int kt = 0; kt < KT; kt++) {
        int cur = kt & 1;
        if (kt + 1 < KT) {
            int k0 = kbase + (kt + 1) * 32;
#pragma unroll
            for (int it = 0; it < 4; it++)
                ra[it] = *(const float4*)(SRC + (long)(arow + it*32)*LD + k0 + acol);
            rb = *(const float4*)(WPTR + (long)(n0 + brow)*LD + k0 + bcol);
        }
#pragma unroll
        for (int ks = 0; ks < 4; ks++) {
            uint32_t a[2][4];
#pragma unroll
            for (int mt = 0; mt < 2; mt++) {
                int m = wm + mt*16;
                a[mt][0] = As[cur][(m+g   )*36 + ks*8 + i4    ];
                a[mt][1] = As[cur][(m+g+8 )*36 + ks*8 + i4    ];
                a[mt][2] = As[cur][(m+g   )*36 + ks*8 + i4 + 4];
                a[mt][3] = As[cur][(m+g+8 )*36 + ks*8 + i4 + 4];
            }
#pragma unroll
            for (int nt = 0; nt < 2; nt++) {
                uint32_t b0 = Bs[cur][(wn+nt*8+g)*36 + ks*8 + i4    ];
                uint32_t b1 = Bs[cur][(wn+nt*8+g)*36 + ks*8 + i4 + 4];
#pragma unroll
                for (int mt = 0; mt < 2; mt++) {
                    asm volatile(
                        "mma.sync.aligned.m16n8k8.row.col.f32.tf32.tf32.f32 "
                        "{%0,%1,%2,%3}, {%4,%5,%6,%7}, {%8,%9}, {%0,%1,%2,%3};\n"
                        : "+f"(accA[mt][nt][0]), "+f"(accA[mt][nt][1]),
                          "+f"(accA[mt][nt][2]), "+f"(accA[mt][nt][3])
                        : "r"(a[mt][0]), "r"(a[mt][1]), "r"(a[mt][2]), "r"(a[mt][3]),
                          "r"(b0), "r"(b1));
                }
            }
        }
        if (kt + 1 < KT) {
            int nxt = 1 - cur;
#pragma unroll
            for (int it = 0; it < 4; it++) {
                int r = arow + it*32;
                As[nxt][r*36+acol+0] = tf32u(ra[it].x); As[nxt][r*36+acol+1] = tf32u(ra[it].y);
                As[nxt][r*36+acol+2] = tf32u(ra[it].z); As[nxt][r*36+acol+3] = tf32u(ra[it].w);
            }
            Bs[nxt][brow*36+bcol+0] = tf32u(rb.x); Bs[nxt][brow*36+bcol+1] = tf32u(rb.y);
            Bs[nxt][brow*36+bcol+2] = tf32u(rb.z); Bs[nxt][brow*36+bcol+3] = tf32u(rb.w);
        }
        __syncthreads();
    }

#pragma unroll
    for (int mt = 0; mt < 2; mt++) {
        int m = wm + mt*16 + g;
#pragma unroll
        for (int nt = 0; nt < 2; nt++) {
            int n = n0 + wn + nt*8 + 2*i4;
            dst[(m  )*768 + n  ] = accA[mt][nt][0];
            dst[(m  )*768 + n+1] = accA[mt][nt][1];
            dst[(m+8)*768 + n  ] = accA[mt][nt][2];
            dst[(m+8)*768 + n+1] = accA[mt][nt][3];
        }
    }
}

// ---------------- K3: GRU combine, emits packed bf16 cat pairs --------------
__global__ void __launch_bounds__(256) gru_kernel(const float* __restrict__ hidden,
        const float* __restrict__ b_ih, const float* __restrict__ b_hh,
        float* __restrict__ out) {
    __shared__ float cat[512];
    int b = blockIdx.x, t = threadIdx.x;
#define SUM4(P, IDX) (P[IDX] + P[(Bb*768)+(IDX)] + P[2*(Bb*768)+(IDX)] + P[3*(Bb*768)+(IDX)])
    int i0 = b*768 + t, i1 = i0 + 256, i2 = i0 + 512;
    float Ar = SUM4(g_gAp, i0) + b_ih[t];
    float Az = SUM4(g_gAp, i1) + b_ih[256+t];
    float An = SUM4(g_gAp, i2) + b_ih[512+t];
    float Br = SUM4(g_gBp, i0) + b_hh[t];
    float Bz = SUM4(g_gBp, i1) + b_hh[256+t];
    float Bn = SUM4(g_gBp, i2) + b_hh[512+t];
#undef SUM4
    float r  = 1.f/(1.f + __expf(-(Ar+Br)));
    float z  = 1.f/(1.f + __expf(-(Az+Bz)));
    float n  = tanhf(An + r*Bn);
    float h  = hidden[b*Hh + t];
    float hn = (1.f - z)*n + z*h;
    out[BV + b*Hh + t] = hn;
    float ctx = g_ctx[b*Hh + t];
    cat[t]       = hn;
    cat[256 + t] = ctx;
    __syncthreads();
    g_catB[b*256 + t] = bf16pack(cat[2*t], cat[2*t+1]);
}

// ---------------- K4: logits bf16 GEMM, all-bf16 smem, cp.async 4-stage -----
// Block: 128(v) x 128(m); 8 warps = 4(m) x 2(n); per-warp 32m x 64v.
// A: packed bf16 pairs. B: packed bf16 k-pairs from g_Wbf — zero cvt in loop.
__global__ void __launch_bounds__(256, 2) gemm_logits(
        const float* __restrict__ outb, float* __restrict__ out) {
    extern __shared__ uint32_t sm[];
    uint32_t* Asm = sm;               // NSTG stages x ASTw (stride 12)
    uint32_t* Bsm = sm + NSTG*ASTw;   // NSTG stages x BSTw (stride 136)

    int blk = blockIdx.x;
    int v0  = blk * 128;
    int tid = threadIdx.x;
    int w = tid >> 5, lane = tid & 31;
    int g = lane >> 2, i4 = lane & 3;
    int wmA = (w >> 1) * 32;
    int wnB = (w & 1) * 64;

    int arow = tid >> 1, ahalf = tid & 1;   // A: 128 rows x 2 16B-chunks
    int bkp = tid >> 5, bcol = (tid & 31)*4; // B: 8 kp-rows x 128 words

    float acc[2][8][4];
#pragma unroll
    for (int mt = 0; mt < 2; mt++)
#pragma unroll
        for (int nt = 0; nt < 8; nt++)
#pragma unroll
            for (int c = 0; c < 4; c++) acc[mt][nt][c] = 0.f;

    uint32_t aDst = (uint32_t)__cvta_generic_to_shared(Asm) + (arow*12 + ahalf*4)*4u;
    uint32_t bDst = (uint32_t)__cvta_generic_to_shared(Bsm) + (bkp*136 + bcol)*4u;
    const uint32_t* aSrc = g_catB + arow*256 + ahalf*4;
    const uint32_t* bSrc = g_Wbf + (long)bkp*Vv + v0 + bcol;

#define ISSUE(ST, KT) do {                                                         \
    uint32_t ad = aDst + (ST)*ASTw*4u;                                             \
    const uint32_t* as_ = aSrc + (KT)*8;                                           \
    asm volatile("cp.async.cg.shared.global [%0], [%1], 16;\n" :: "r"(ad), "l"(as_)); \
    uint32_t bd = bDst + (ST)*BSTw*4u;                                             \
    const uint32_t* bs_ = bSrc + (long)(KT)*8*Vv;                                  \
    asm volatile("cp.async.cg.shared.global [%0], [%1], 16;\n" :: "r"(bd), "l"(bs_)); \
    asm volatile("cp.async.commit_group;\n");                                      \
} while (0)

    ISSUE(0, 0); ISSUE(1, 1); ISSUE(2, 2);

    for (int kt = 0; kt < 32; kt++) {
        int st = kt & 3;
        asm volatile("cp.async.wait_group 2;\n" ::: "memory");
        __syncthreads();
        if (kt + 3 < 32) ISSUE((kt + 3) & 3, kt + 3);
        else asm volatile("cp.async.commit_group;\n");   // keep group count stable
        const uint32_t* A_ = Asm + st*ASTw;
        const uint32_t* B_ = Bsm + st*BSTw;
        uint32_t a[2][4];
#pragma unroll
        for (int mt = 0; mt < 2; mt++) {
            int m = wmA + mt*16;
            a[mt][0] = A_[(m+g   )*12 + i4    ];
            a[mt][1] = A_[(m+g+8 )*12 + i4    ];
            a[mt][2] = A_[(m+g   )*12 + i4 + 4];
            a[mt][3] = A_[(m+g+8 )*12 + i4 + 4];
        }
#pragma unroll
        for (int nt = 0; nt < 8; nt++) {
            int vr = wnB + nt*8 + g;
            uint32_t b0 = B_[(i4    )*136 + vr];
            uint32_t b1 = B_[(i4 + 4)*136 + vr];
#pragma unroll
            for (int mt = 0; mt < 2; mt++) {
                asm volatile(
                    "mma.sync.aligned.m16n8k16.row.col.f32.bf16.bf16.f32 "
                    "{%0,%1,%2,%3}, {%4,%5,%6,%7}, {%8,%9}, {%0,%1,%2,%3};\n"
                    : "+f"(acc[mt][nt][0]), "+f"(acc[mt][nt][1]),
                      "+f"(acc[mt][nt][2]), "+f"(acc[mt][nt][3])
                    : "r"(a[mt][0]), "r"(a[mt][1]), "r"(a[mt][2]), "r"(a[mt][3]),
                      "r"(b0), "r"(b1));
            }
        }
    }
#undef ISSUE

    // epilogue: bias, store logits, fused partial log-softmax (per 64-col half)
    float ob0s[8], ob1s[8];
#pragma unroll
    for (int nt = 0; nt < 8; nt++) {
        int v = v0 + wnB + nt*8 + 2*i4;
        ob0s[nt] = outb[v]; ob1s[nt] = outb[v+1];
    }
    float mx[2][2] = {{-1e30f,-1e30f},{-1e30f,-1e30f}};
#pragma unroll
    for (int mt = 0; mt < 2; mt++) {
        long ro = (long)(wmA + mt*16 + g)*Vv;
#pragma unroll
        for (int nt = 0; nt < 8; nt++) {
            int v = v0 + wnB + nt*8 + 2*i4;
            float r0 = acc[mt][nt][0]+ob0s[nt], r1 = acc[mt][nt][1]+ob1s[nt];
            float r2 = acc[mt][nt][2]+ob0s[nt], r3 = acc[mt][nt][3]+ob1s[nt];
            *(float2*)(out + ro + v)          = make_float2(r0, r1);
            *(float2*)(out + ro + 8L*Vv + v)  = make_float2(r2, r3);
            mx[mt][0] = fmaxf(mx[mt][0], fmaxf(r0, r1));
            mx[mt][1] = fmaxf(mx[mt][1], fmaxf(r2, r3));
        }
    }
    float ss[2][2] = {{0.f,0.f},{0.f,0.f}};
#pragma unroll
    for (int mt = 0; mt < 2; mt++)
#pragma unroll
        for (int nt = 0; nt < 8; nt++) {
            ss[mt][0] += __expf(acc[mt][nt][0]+ob0s[nt]-mx[mt][0])
                       + __expf(acc[mt][nt][1]+ob1s[nt]-mx[mt][0]);
            ss[mt][1] += __expf(acc[mt][nt][2]+ob0s[nt]-mx[mt][1])
                       + __expf(acc[mt][nt][3]+ob1s[nt]-mx[mt][1]);
        }
#pragma unroll
    for (int o = 1; o <= 2; o <<= 1) {
#pragma unroll
        for (int mt = 0; mt < 2; mt++)
#pragma unroll
            for (int hh = 0; hh < 2; hh++) {
                float om = __shfl_xor_sync(0xffffffffu, mx[mt][hh], o);
                float os = __shfl_xor_sync(0xffffffffu, ss[mt][hh], o);
                float nm = fmaxf(mx[mt][hh], om);
                ss[mt][hh] = ss[mt][hh]*__expf(mx[mt][hh]-nm) + os*__expf(om-nm);
                mx[mt][hh] = nm;
            }
    }
    if (i4 == 0) {
        int pc = blk*2 + (w & 1);
#pragma unroll
        for (int mt = 0; mt < 2; mt++)
#pragma unroll
            for (int hh = 0; hh < 2; hh++) {
                int row = wmA + mt*16 + g + hh*8;
                g_pM[row*NP + pc] = mx[mt][hh];
                g_pL[row*NP + pc] = ss[mt][hh];
            }
    }
}

// ---------------- K5: fused merge + subtract (512 blocks, quarter-row each) -
__global__ void __launch_bounds__(256) lse_sub(float* __restrict__ out) {
    __shared__ float redm[8], reds[8];
    __shared__ float s_lse;
    int b = blockIdx.x >> 2, q = blockIdx.x & 3;
    int tid = threadIdx.x;
    float m = -1e30f, l = 0.f;
    for (int p = tid; p < NP; p += 256) {
        float pm = g_pM[b*NP + p], pl = g_pL[b*NP + p];
        float nm = fmaxf(m, pm);
        l = l*__expf(m-nm) + pl*__expf(pm-nm);
        m = nm;
    }
#pragma unroll
    for (int o = 16; o; o >>= 1) {
        float om = __shfl_xor_sync(0xffffffffu, m, o);
        float ol = __shfl_xor_sync(0xffffffffu, l, o);
        float nm = fmaxf(m, om);
        l = l*__expf(m-nm) + ol*__expf(om-nm);
        m = nm;
    }
    if ((tid & 31) == 0) { redm[tid>>5] = m; reds[tid>>5] = l; }
    __syncthreads();
    if (tid == 0) {
        float M = -1e30f, L = 0.f;
        for (int i = 0; i < 8; i++) {
            float nm = fmaxf(M, redm[i]);
            L = L*__expf(M-nm) + reds[i]*__expf(redm[i]-nm);
            M = nm;
        }
        s_lse = M + logf(L);
    }
    __syncthreads();
    float lse = s_lse;
    float4* row = (float4*)(out + (long)b*Vv) + q*2000;
    for (int t = tid; t < 2000; t += 256) {
        float4 x = row[t];
        x.x -= lse; x.y -= lse; x.z -= lse; x.w -= lse;
        row[t] = x;
    }
}

// ---------------- launch ---------------------------------------------------
extern "C" void kernel_launch(void* const* d_in, const int* in_sizes, int n_in,
                              void* d_out, int out_size) {
    (void)in_sizes; (void)n_in; (void)out_size;
    const int*   ids    = (const int*)  d_in[0];
    const float* hidden = (const float*)d_in[1];
    const float* enc    = (const float*)d_in[2];
    const float* emb    = (const float*)d_in[3];
    const float* attnW  = (const float*)d_in[4];
    // d_in[5] = attn_b: per-batch constant in softmax argument — cancels.
    const float* W_ih   = (const float*)d_in[6];
    const float* W_hh   = (const float*)d_in[7];
    const float* b_ih   = (const float*)d_in[8];
    const float* b_hh   = (const float*)d_in[9];
    const float* outW   = (const float*)d_in[10];
    const float* outb   = (const float*)d_in[11];
    float* out = (float*)d_out;

    static bool attr_done = false;
    if (!attr_done) {
        cudaFuncSetAttribute(gemm_logits,
                             cudaFuncAttributeMaxDynamicSharedMemorySize, SMEMB);
        attr_done = true;
    }

    attn_partial<<<dim3(9, Bb), 512>>>(enc, hidden, attnW, outW, W_ih, W_hh);
    attn_combine<<<Bb, 256>>>(ids, emb, out);
    gates_mma<<<dim3(24, 2, 4), 256>>>(hidden, W_ih, W_hh);
    gru_kernel<<<Bb, 256>>>(hidden, b_ih, b_hh, out);
    gemm_logits<<<NBLK, 256, SMEMB>>>(outb, out);
    lse_sub<<<Bb*4, 256>>>(out);
}

// round 16
// speedup vs baseline: 1.1623x; 1.1623x over previous
#include <cuda_runtime.h>
#include <cuda_bf16.h>
#include <cstdint>

#define Vv 32000
#define Hh 256
#define Ss 2048
#define Bb 128
#define BV (Bb*Vv)
#define NBLK 250           // gemm_logits blocks
#define NP   (NBLK*2)      // partial-softmax columns per row (2 n-halves/block)
#define KSPLIT 8           // gates split-K factor

// gemm_logits smem: 4 stages * (A 128x12 + B 16x132) words
#define ASTw 1536          // words per A stage (128*12) — bf16 pairs, stride 12
#define BSTw 2112          // words per B stage (16*132) — fp32, stride 132
#define NSTG 4
#define SMEMB (NSTG*(ASTw+BSTw)*4)

// ---------------- scratch (static __device__, no allocation) ----------------
__device__ float g_q[Bb*Hh];
__device__ float g_ctx[Bb*Hh];
__device__ float g_xcat[Bb*512];
__device__ float g_scores[Bb*Ss];
__device__ float g_partM[Bb*4];
__device__ float g_partL[Bb*4];
__device__ float g_ctxPart[Bb*4*Hh];
__device__ float g_gAp[KSPLIT*Bb*768];   // split-K partials (no bias)
__device__ float g_gBp[KSPLIT*Bb*768];
__device__ float g_pM[Bb*NP];       // per-block logit max partials
__device__ float g_pL[Bb*NP];       // per-block sumexp partials
__device__ __align__(16) uint32_t g_catB[Bb*256];   // [h_new, ctx] as packed bf16x2

__device__ __forceinline__ uint32_t tf32u(float x) {
    uint32_t u;
    asm("cvt.rna.tf32.f32 %0, %1;" : "=r"(u) : "f"(x));
    return u;
}

__device__ __forceinline__ uint32_t bf16pack(float lo, float hi) {
    uint32_t r;
    asm("cvt.rn.bf16x2.f32 %0, %1, %2;" : "=r"(r) : "f"(hi), "f"(lo));
    return r;
}

__device__ __forceinline__ void l2_prefetch(const void* p) {
    asm volatile("prefetch.global.L2 [%0];" :: "l"(p));
}

// ---------------- K0: q[b,h] = sum_k h[b,k] * We[k,h]  (We = attn_W[:,H:]) ----
__global__ void __launch_bounds__(256) q_kernel(const float* __restrict__ hidden,
                                                const float* __restrict__ attnW) {
    int b = blockIdx.x, h = threadIdx.x;
    __shared__ float hs[Hh];
    hs[h] = hidden[b*Hh + h];
    __syncthreads();
    float acc = 0.f;
#pragma unroll 8
    for (int k = 0; k < Hh; k++) acc += hs[k] * attnW[k*(2*Hh) + Hh + h];
    g_q[b*Hh + h] = acc;
}

// ---------------- K1a: flash attention partials + L2 prefetch of weights ----
__global__ void __launch_bounds__(512) attn_partial(const float* __restrict__ enc,
        const float* __restrict__ outW, const float* __restrict__ W_ih,
        const float* __restrict__ W_hh) {
    int b = blockIdx.y, sc = blockIdx.x;
    int tid = threadIdx.x;

    if (sc >= 4) {
        if (sc < 6) {
            int pid = (sc - 4)*Bb + b;
            const float* src = outW + (long)pid*64000;
            for (int t = tid; t < 2000; t += 512)
                l2_prefetch(src + t*32);
        } else {
            const float* s1 = W_ih + (long)b*3072;
            for (int t = tid; t < 96; t += 512)
                l2_prefetch(s1 + t*32);
            const float* s2 = W_hh + (long)b*1536;
            for (int t = tid; t < 48; t += 512)
                l2_prefetch(s2 + t*32);
        }
        return;
    }

    int w = tid >> 5, lane = tid & 31;
    __shared__ float qs[Hh];
    __shared__ float wm[16], wl[16];
    __shared__ float wctx[16][Hh];
    if (tid < Hh) qs[tid] = g_q[b*Hh + tid];
    __syncthreads();
    float qv[8];
#pragma unroll
    for (int k = 0; k < 8; k++) qv[k] = qs[lane*8 + k];

    const float* encb = enc + (long)b*Hh + (long)sc*512*(Bb*Hh) + lane*8;
    float m = -1e30f, l = 0.f;
    float c[8];
#pragma unroll
    for (int k = 0; k < 8; k++) c[k] = 0.f;

    for (int j0 = 0; j0 < 32; j0 += 4) {
        float e[4][8];
#pragma unroll
        for (int jj = 0; jj < 4; jj++) {
            const float* p = encb + (long)(w + 16*(j0+jj))*(Bb*Hh);
            float4 x0 = __ldcs((const float4*)p);
            float4 x1 = __ldcs((const float4*)(p+4));
            e[jj][0]=x0.x; e[jj][1]=x0.y; e[jj][2]=x0.z; e[jj][3]=x0.w;
            e[jj][4]=x1.x; e[jj][5]=x1.y; e[jj][6]=x1.z; e[jj][7]=x1.w;
        }
#pragma unroll
        for (int jj = 0; jj < 4; jj++) {
            float part = 0.f;
#pragma unroll
            for (int k = 0; k < 8; k++) part += e[jj][k]*qv[k];
#pragma unroll
            for (int o = 16; o; o >>= 1) part += __shfl_xor_sync(0xffffffffu, part, o);
            if (lane == 0) g_scores[b*Ss + sc*512 + w + 16*(j0+jj)] = part;
            float nm  = fmaxf(m, part);
            float scl = __expf(m - nm);
            float p_  = __expf(part - nm);
            l = l*scl + p_;
#pragma unroll
            for (int k = 0; k < 8; k++) c[k] = c[k]*scl + p_*e[jj][k];
            m = nm;
        }
    }
    if (lane == 0) { wm[w] = m; wl[w] = l; }
#pragma unroll
    for (int k = 0; k < 8; k++) wctx[w][lane*8+k] = c[k];
    __syncthreads();
    if (tid < Hh) {
        float gm = -1e30f;
        for (int i = 0; i < 16; i++) gm = fmaxf(gm, wm[i]);
        float L = 0.f, cv = 0.f;
        for (int i = 0; i < 16; i++) {
            float f = __expf(wm[i] - gm);
            L  += wl[i]*f;
            cv += wctx[i][tid]*f;
        }
        g_ctxPart[(b*4+sc)*Hh + tid] = cv;
        if (tid == 0) { g_partM[b*4+sc] = gm; g_partL[b*4+sc] = L; }
    }
}

// ---------------- K1b: combine partials, write attn_weights + context + xcat
__global__ void __launch_bounds__(256) attn_combine(const int* __restrict__ ids,
                                                    const float* __restrict__ emb,
                                                    float* __restrict__ out) {
    int b = blockIdx.x, tid = threadIdx.x;
    float m0 = g_partM[b*4+0], m1 = g_partM[b*4+1], m2 = g_partM[b*4+2], m3 = g_partM[b*4+3];
    float gm = fmaxf(fmaxf(m0,m1), fmaxf(m2,m3));
    float f0 = __expf(m0-gm), f1 = __expf(m1-gm), f2 = __expf(m2-gm), f3 = __expf(m3-gm);
    float L = g_partL[b*4+0]*f0 + g_partL[b*4+1]*f1 + g_partL[b*4+2]*f2 + g_partL[b*4+3]*f3;
    float cv = g_ctxPart[(b*4+0)*Hh+tid]*f0 + g_ctxPart[(b*4+1)*Hh+tid]*f1
             + g_ctxPart[(b*4+2)*Hh+tid]*f2 + g_ctxPart[(b*4+3)*Hh+tid]*f3;
    float ctx = cv / L;
    g_ctx[b*Hh + tid] = ctx;
    g_xcat[b*512 + tid]       = emb[(long)ids[b]*Hh + tid];
    g_xcat[b*512 + 256 + tid] = ctx;
    float invL = 1.f / L;
    for (int s = tid; s < Ss; s += 256)
        out[BV + Bb*Hh + b*Ss + s] = __expf(g_scores[b*Ss+s] - gm) * invL;
}

// ---------------- K2: gates TF32 GEMM, split-K x8 ---------------------------
// grid (24, 2, 8). phase 0: K=512 -> 8 chunks of 64. phase 1: K=256 -> 8 of 32.
__global__ void __launch_bounds__(256) gates_mma(const float* __restrict__ hidden,
        const float* __restrict__ W_ih, const float* __restrict__ W_hh) {
    __shared__ uint32_t As[2][128*36];
    __shared__ uint32_t Bs[2][32*36];

    int phase = blockIdx.y, z = blockIdx.z;
    const float* SRC  = phase ? hidden : g_xcat;
    const float* WPTR = phase ? W_hh   : W_ih;
    float*       dst  = (phase ? g_gBp : g_gAp) + z*(Bb*768);
    int LD = phase ? 256 : 512;
    int KT = phase ? 1   : 2;          // k-tiles of 32 per chunk
    int kbase = z * KT * 32;

    int n0  = blockIdx.x * 32;
    int tid = threadIdx.x;
    int w = tid >> 5, lane = tid & 31;
    int wm = (w >> 1) * 32, wn = (w & 1) * 16;
    int g = lane >> 2, i4 = lane & 3;

    int arow = tid >> 3, acol = (tid & 7) * 4;
    int brow = tid >> 3, bcol = (tid & 7) * 4;

    float accA[2][2][4];
#pragma unroll
    for (int mt = 0; mt < 2; mt++)
#pragma unroll
        for (int nt = 0; nt < 2; nt++)
#pragma unroll
            for (int c = 0; c < 4; c++) accA[mt][nt][c] = 0.f;

    float4 ra[4]; float4 rb;
#pragma unroll
    for (int it = 0; it < 4; it++)
        ra[it] = *(const float4*)(SRC + (long)(arow + it*32)*LD + kbase + acol);
    rb = *(const float4*)(WPTR + (long)(n0 + brow)*LD + kbase + bcol);
#pragma unroll
    for (int it = 0; it < 4; it++) {
        int r = arow + it*32;
        As[0][r*36+acol+0] = tf32u(ra[it].x); As[0][r*36+acol+1] = tf32u(ra[it].y);
        As[0][r*36+acol+2] = tf32u(ra[it].z); As[0][r*36+acol+3] = tf32u(ra[it].w);
    }
    Bs[0][brow*36+bcol+0] = tf32u(rb.x); Bs[0][brow*36+bcol+1] = tf32u(rb.y);
    Bs[0][brow*36+bcol+2] = tf32u(rb.z); Bs[0][brow*36+bcol+3] = tf32u(rb.w);
    __syncthreads();

    for (int kt = 0; kt < KT; kt++) {
        int cur = kt & 1;
        if (kt + 1 < KT) {
            int k0 = kbase + (kt + 1) * 32;
#pragma unroll
            for (int it = 0; it < 4; it++)
                ra[it] = *(const float4*)(SRC + (long)(arow + it*32)*LD + k0 + acol);
            rb = *(const float4*)(WPTR + (long)(n0 + brow)*LD + k0 + bcol);
        }
#pragma unroll
        for (int ks = 0; ks < 4; ks++) {
            uint32_t a[2][4];
#pragma unroll
            for (int mt = 0; mt < 2; mt++) {
                int m = wm + mt*16;
                a[mt][0] = As[cur][(m+g   )*36 + ks*8 + i4    ];
                a[mt][1] = As[cur][(m+g+8 )*36 + ks*8 + i4    ];
                a[mt][2] = As[cur][(m+g   )*36 + ks*8 + i4 + 4];
                a[mt][3] = As[cur][(m+g+8 )*36 + ks*8 + i4 + 4];
            }
#pragma unroll
            for (int nt = 0; nt < 2; nt++) {
                uint32_t b0 = Bs[cur][(wn+nt*8+g)*36 + ks*8 + i4    ];
                uint32_t b1 = Bs[cur][(wn+nt*8+g)*36 + ks*8 + i4 + 4];
#pragma unroll
                for (int mt = 0; mt < 2; mt++) {
                    asm volatile(
                        "mma.sync.aligned.m16n8k8.row.col.f32.tf32.tf32.f32 "
                        "{%0,%1,%2,%3}, {%4,%5,%6,%7}, {%8,%9}, {%0,%1,%2,%3};\n"
                        : "+f"(accA[mt][nt][0]), "+f"(accA[mt][nt][1]),
                          "+f"(accA[mt][nt][2]), "+f"(accA[mt][nt][3])
                        : "r"(a[mt][0]), "r"(a[mt][1]), "r"(a[mt][2]), "r"(a[mt][3]),
                          "r"(b0), "r"(b1));
                }
            }
        }
        if (kt + 1 < KT) {
            int nxt = 1 - cur;
#pragma unroll
            for (int it = 0; it < 4; it++) {
                int r = arow + it*32;
                As[nxt][r*36+acol+0] = tf32u(ra[it].x); As[nxt][r*36+acol+1] = tf32u(ra[it].y);
                As[nxt][r*36+acol+2] = tf32u(ra[it].z); As[nxt][r*36+acol+3] = tf32u(ra[it].w);
            }
            Bs[nxt][brow*36+bcol+0] = tf32u(rb.x); Bs[nxt][brow*36+bcol+1] = tf32u(rb.y);
            Bs[nxt][brow*36+bcol+2] = tf32u(rb.z); Bs[nxt][brow*36+bcol+3] = tf32u(rb.w);
        }
        __syncthreads();
    }

#pragma unroll
    for (int mt = 0; mt < 2; mt++) {
        int m = wm + mt*16 + g;
#pragma unroll
        for (int nt = 0; nt < 2; nt++) {
            int n = n0 + wn + nt*8 + 2*i4;
            dst[(m  )*768 + n  ] = accA[mt][nt][0];
            dst[(m  )*768 + n+1] = accA[mt][nt][1];
            dst[(m+8)*768 + n  ] = accA[mt][nt][2];
            dst[(m+8)*768 + n+1] = accA[mt][nt][3];
        }
    }
}

// ---------------- K3: GRU combine (768 thr: 1 gate element/thread) ----------
__global__ void __launch_bounds__(768) gru_kernel(const float* __restrict__ hidden,
        const float* __restrict__ b_ih, const float* __restrict__ b_hh,
        float* __restrict__ out) {
    __shared__ float sA[768], sB[768], cat[512];
    int b = blockIdx.x, t = threadIdx.x;
    long base = (long)b*768 + t;
    float A = 0.f, Bv = 0.f;
#pragma unroll
    for (int z = 0; z < KSPLIT; z++) {
        A  += g_gAp[(long)z*(Bb*768) + base];
        Bv += g_gBp[(long)z*(Bb*768) + base];
    }
    sA[t] = A + b_ih[t];
    sB[t] = Bv + b_hh[t];
    __syncthreads();
    if (t < 256) {
        float r  = 1.f/(1.f + __expf(-(sA[t] + sB[t])));
        float z_ = 1.f/(1.f + __expf(-(sA[256+t] + sB[256+t])));
        float n  = tanhf(sA[512+t] + r*sB[512+t]);
        float h  = hidden[b*Hh + t];
        float hn = (1.f - z_)*n + z_*h;
        out[BV + b*Hh + t] = hn;
        cat[t]       = hn;
        cat[256 + t] = g_ctx[b*Hh + t];
    }
    __syncthreads();
    if (t < 256) g_catB[b*256 + t] = bf16pack(cat[2*t], cat[2*t+1]);
}

// ---------------- K4: logits bf16 GEMM, cp.async 4-stage, 1 sync/tile -------
// Block: 128(v) x 128(m); 8 warps = 4(m) x 2(n); per-warp 32m x 64v.
__global__ void __launch_bounds__(256, 2) gemm_logits(const float* __restrict__ outW,
        const float* __restrict__ outb, float* __restrict__ out) {
    extern __shared__ uint32_t sm[];
    uint32_t* Asm = sm;               // NSTG stages x ASTw (bf16 pairs, stride 12)
    uint32_t* Bsm = sm + NSTG*ASTw;   // NSTG stages x BSTw (fp32, stride 132)

    int blk = blockIdx.x;
    int v0  = blk * 128;
    int tid = threadIdx.x;
    int w = tid >> 5, lane = tid & 31;
    int g = lane >> 2, i4 = lane & 3;
    int wmA = (w >> 1) * 32;
    int wnB = (w & 1) * 64;

    int arow = tid >> 1, ahalf = tid & 1;   // A: 128 rows x 2 16B-chunks
    int kk = tid >> 4, vv = (tid & 15)*8;   // B: 16 k-rows x (2x16B per thread)

    float acc[2][8][4];
#pragma unroll
    for (int mt = 0; mt < 2; mt++)
#pragma unroll
        for (int nt = 0; nt < 8; nt++)
#pragma unroll
            for (int c = 0; c < 4; c++) acc[mt][nt][c] = 0.f;

    uint32_t aDst = (uint32_t)__cvta_generic_to_shared(Asm) + (arow*12 + ahalf*4)*4u;
    uint32_t bDst = (uint32_t)__cvta_generic_to_shared(Bsm) + (kk*132 + vv)*4u;
    const uint32_t* aSrc = g_catB + arow*256 + ahalf*4;

#define ISSUE(ST, KT) do {                                                         \
    uint32_t ad = aDst + (ST)*ASTw*4u;                                             \
    const uint32_t* as_ = aSrc + (KT)*8;                                           \
    asm volatile("cp.async.cg.shared.global [%0], [%1], 16;\n" :: "r"(ad), "l"(as_)); \
    uint32_t bd = bDst + (ST)*BSTw*4u;                                             \
    const float* bs_ = outW + (long)((KT)*16 + kk)*Vv + v0 + vv;                   \
    asm volatile("cp.async.cg.shared.global [%0], [%1], 16;\n" :: "r"(bd), "l"(bs_)); \
    asm volatile("cp.async.cg.shared.global [%0], [%1], 16;\n" :: "r"(bd+16), "l"(bs_+4)); \
    asm volatile("cp.async.commit_group;\n");                                      \
} while (0)

    ISSUE(0, 0); ISSUE(1, 1); ISSUE(2, 2);

    for (int kt = 0; kt < 32; kt++) {
        int st = kt & 3;
        asm volatile("cp.async.wait_group 2;\n" ::: "memory");
        __syncthreads();
        if (kt + 3 < 32) ISSUE((kt + 3) & 3, kt + 3);
        else asm volatile("cp.async.commit_group;\n");   // keep group count stable
        const uint32_t* A_ = Asm + st*ASTw;
        const float*    B_ = (const float*)(Bsm + st*BSTw);
        uint32_t a[2][4];
#pragma unroll
        for (int mt = 0; mt < 2; mt++) {
            int m = wmA + mt*16;
            a[mt][0] = A_[(m+g   )*12 + i4    ];
            a[mt][1] = A_[(m+g+8 )*12 + i4    ];
            a[mt][2] = A_[(m+g   )*12 + i4 + 4];
            a[mt][3] = A_[(m+g+8 )*12 + i4 + 4];
        }
#pragma unroll
        for (int nt = 0; nt < 8; nt++) {
            int vr = wnB + nt*8 + g;
            float f0 = B_[(2*i4    )*132 + vr];
            float f1 = B_[(2*i4 + 1)*132 + vr];
            float f2 = B_[(2*i4 + 8)*132 + vr];
            float f3 = B_[(2*i4 + 9)*132 + vr];
            uint32_t b0 = bf16pack(f0, f1);
            uint32_t b1 = bf16pack(f2, f3);
#pragma unroll
            for (int mt = 0; mt < 2; mt++) {
                asm volatile(
                    "mma.sync.aligned.m16n8k16.row.col.f32.bf16.bf16.f32 "
                    "{%0,%1,%2,%3}, {%4,%5,%6,%7}, {%8,%9}, {%0,%1,%2,%3};\n"
                    : "+f"(acc[mt][nt][0]), "+f"(acc[mt][nt][1]),
                      "+f"(acc[mt][nt][2]), "+f"(acc[mt][nt][3])
                    : "r"(a[mt][0]), "r"(a[mt][1]), "r"(a[mt][2]), "r"(a[mt][3]),
                      "r"(b0), "r"(b1));
            }
        }
    }
#undef ISSUE

    // epilogue: bias, store logits, fused partial log-softmax (per 64-col half)
    float ob0s[8], ob1s[8];
#pragma unroll
    for (int nt = 0; nt < 8; nt++) {
        int v = v0 + wnB + nt*8 + 2*i4;
        ob0s[nt] = outb[v]; ob1s[nt] = outb[v+1];
    }
    float mx[2][2] = {{-1e30f,-1e30f},{-1e30f,-1e30f}};
#pragma unroll
    for (int mt = 0; mt < 2; mt++) {
        long ro = (long)(wmA + mt*16 + g)*Vv;
#pragma unroll
        for (int nt = 0; nt < 8; nt++) {
            int v = v0 + wnB + nt*8 + 2*i4;
            float r0 = acc[mt][nt][0]+ob0s[nt], r1 = acc[mt][nt][1]+ob1s[nt];
            float r2 = acc[mt][nt][2]+ob0s[nt], r3 = acc[mt][nt][3]+ob1s[nt];
            *(float2*)(out + ro + v)          = make_float2(r0, r1);
            *(float2*)(out + ro + 8L*Vv + v)  = make_float2(r2, r3);
            mx[mt][0] = fmaxf(mx[mt][0], fmaxf(r0, r1));
            mx[mt][1] = fmaxf(mx[mt][1], fmaxf(r2, r3));
        }
    }
    float ss[2][2] = {{0.f,0.f},{0.f,0.f}};
#pragma unroll
    for (int mt = 0; mt < 2; mt++)
#pragma unroll
        for (int nt = 0; nt < 8; nt++) {
            ss[mt][0] += __expf(acc[mt][nt][0]+ob0s[nt]-mx[mt][0])
                       + __expf(acc[mt][nt][1]+ob1s[nt]-mx[mt][0]);
            ss[mt][1] += __expf(acc[mt][nt][2]+ob0s[nt]-mx[mt][1])
                       + __expf(acc[mt][nt][3]+ob1s[nt]-mx[mt][1]);
        }
#pragma unroll
    for (int o = 1; o <= 2; o <<= 1) {
#pragma unroll
        for (int mt = 0; mt < 2; mt++)
#pragma unroll
            for (int hh = 0; hh < 2; hh++) {
                float om = __shfl_xor_sync(0xffffffffu, mx[mt][hh], o);
                float os = __shfl_xor_sync(0xffffffffu, ss[mt][hh], o);
                float nm = fmaxf(mx[mt][hh], om);
                ss[mt][hh] = ss[mt][hh]*__expf(mx[mt][hh]-nm) + os*__expf(om-nm);
                mx[mt][hh] = nm;
            }
    }
    if (i4 == 0) {
        int pc = blk*2 + (w & 1);
#pragma unroll
        for (int mt = 0; mt < 2; mt++)
#pragma unroll
            for (int hh = 0; hh < 2; hh++) {
                int row = wmA + mt*16 + g + hh*8;
                g_pM[row*NP + pc] = mx[mt][hh];
                g_pL[row*NP + pc] = ss[mt][hh];
            }
    }
}

// ---------------- K5: fused merge + subtract (512 blocks, quarter-row each) -
__global__ void __launch_bounds__(256) lse_sub(float* __restrict__ out) {
    __shared__ float redm[8], reds[8];
    __shared__ float s_lse;
    int b = blockIdx.x >> 2, q = blockIdx.x & 3;
    int tid = threadIdx.x;
    float m = -1e30f, l = 0.f;
    for (int p = tid; p < NP; p += 256) {
        float pm = g_pM[b*NP + p], pl = g_pL[b*NP + p];
        float nm = fmaxf(m, pm);
        l = l*__expf(m-nm) + pl*__expf(pm-nm);
        m = nm;
    }
#pragma unroll
    for (int o = 16; o; o >>= 1) {
        float om = __shfl_xor_sync(0xffffffffu, m, o);
        float ol = __shfl_xor_sync(0xffffffffu, l, o);
        float nm = fmaxf(m, om);
        l = l*__expf(m-nm) + ol*__expf(om-nm);
        m = nm;
    }
    if ((tid & 31) == 0) { redm[tid>>5] = m; reds[tid>>5] = l; }
    __syncthreads();
    if (tid == 0) {
        float M = -1e30f, L = 0.f;
        for (int i = 0; i < 8; i++) {
            float nm = fmaxf(M, redm[i]);
            L = L*__expf(M-nm) + reds[i]*__expf(redm[i]-nm);
            M = nm;
        }
        s_lse = M + logf(L);
    }
    __syncthreads();
    float lse = s_lse;
    float4* row = (float4*)(out + (long)b*Vv) + q*2000;
    for (int t = tid; t < 2000; t += 256) {
        float4 x = row[t];
        x.x -= lse; x.y -= lse; x.z -= lse; x.w -= lse;
        row[t] = x;
    }
}

// ---------------- launch ---------------------------------------------------
extern "C" void kernel_launch(void* const* d_in, const int* in_sizes, int n_in,
                              void* d_out, int out_size) {
    (void)in_sizes; (void)n_in; (void)out_size;
    const int*   ids    = (const int*)  d_in[0];
    const float* hidden = (const float*)d_in[1];
    const float* enc    = (const float*)d_in[2];
    const float* emb    = (const float*)d_in[3];
    const float* attnW  = (const float*)d_in[4];
    // d_in[5] = attn_b: per-batch constant in softmax argument — cancels.
    const float* W_ih   = (const float*)d_in[6];
    const float* W_hh   = (const float*)d_in[7];
    const float* b_ih   = (const float*)d_in[8];
    const float* b_hh   = (const float*)d_in[9];
    const float* outW   = (const float*)d_in[10];
    const float* outb   = (const float*)d_in[11];
    float* out = (float*)d_out;

    static bool attr_done = false;
    if (!attr_done) {
        cudaFuncSetAttribute(gemm_logits,
                             cudaFuncAttributeMaxDynamicSharedMemorySize, SMEMB);
        attr_done = true;
    }

    q_kernel<<<Bb, 256>>>(hidden, attnW);
    attn_partial<<<dim3(7, Bb), 512>>>(enc, outW, W_ih, W_hh);
    attn_combine<<<Bb, 256>>>(ids, emb, out);
    gates_mma<<<dim3(24, 2, KSPLIT), 256>>>(hidden, W_ih, W_hh);
    gru_kernel<<<Bb, 768>>>(hidden, b_ih, b_hh, out);
    gemm_logits<<<NBLK, 256, SMEMB>>>(outW, outb, out);
    lse_sub<<<Bb*4, 256>>>(out);
}